// round 13
// baseline (speedup 1.0000x reference)
#include <cuda_runtime.h>
#include <cuda_fp16.h>
#include <cstdint>

// Shapes (fixed for KANLayer_17265768530645)
#define B_SZ    8192
#define D_IN    512
#define D_OUT   128
#define X_MIN_F (-3.0f)
#define DENOM   6.00000001f
#define SCALE_F (15.0f / DENOM)

// GEMM: y[b,n] = sum_{k'} C[b,k'] * W'[n,k'],  K' = 8704 (544 ksteps of 16).
// kstep ks < 512: spline, feature i = ks, C = hat pair {1-f,f} at (k0,k0+1).
// kstep ks >= 512: skip, C = x features 16*ks-8192 .. +15.
#define KSTEPS   544

// W' as mma B-fragments, chunk-major (validated R10-R12).
__device__ __align__(128) uint4 g_wf[KSTEPS * 4 * 2 * 32];          // 2.2 MB
// Spline code table, TRANSPOSED [i][b]: .x = (f_h<<16)|onemf_h, .y = k0.
__device__ __align__(16)  uint2 g_enc[(size_t)D_IN * B_SZ];          // 32 MB
// fp16 copy of x, row-major [b][i] (for skip ksteps).
__device__ __align__(16)  __half g_xh[(size_t)B_SZ * D_IN];          // 8 MB
// K-split partial outputs: [2][B][128] fp32.
__device__ __align__(16)  float g_part[2 * (size_t)B_SZ * D_OUT];    // 8.4 MB

// ---------------- PTX helpers -----------------------------------------------
__device__ __forceinline__ void mma16816(float* c, const uint32_t* a,
                                         uint32_t b0, uint32_t b1) {
    asm volatile(
        "mma.sync.aligned.m16n8k16.row.col.f32.f16.f16.f32 "
        "{%0,%1,%2,%3}, {%4,%5,%6,%7}, {%8,%9}, {%0,%1,%2,%3};"
        : "+f"(c[0]), "+f"(c[1]), "+f"(c[2]), "+f"(c[3])
        : "r"(a[0]), "r"(a[1]), "r"(a[2]), "r"(a[3]), "r"(b0), "r"(b1));
}
__device__ __forceinline__ uint32_t h2u(__half2 h) {
    return *reinterpret_cast<uint32_t*>(&h);
}

// ---------------------------------------------------------------------------
// W' prep (validated R7-R12, unchanged).
// ---------------------------------------------------------------------------
__global__ void kan_wprep(const float* __restrict__ w,    // (128, 512, 16)
                          const float* __restrict__ s)    // (128, 512)
{
    const int wc   = blockIdx.y;
    const int lane = threadIdx.x & 31;
    const int ks   = blockIdx.x * 4 + (threadIdx.x >> 5);

    uint32_t r[8];
    #pragma unroll
    for (int nf = 0; nf < 4; nf++) {
        const int n = wc * 32 + nf * 8 + (lane >> 2);
        #pragma unroll
        for (int h = 0; h < 2; h++) {
            const int k = ks * 16 + (lane & 3) * 2 + h * 8;
            float v0, v1;
            if (ks < 512) {
                v0 = w[(size_t)n * 8192 + k];
                v1 = w[(size_t)n * 8192 + k + 1];
            } else {
                const int kk = k - 8192;
                v0 = s[(size_t)n * 512 + kk];
                v1 = s[(size_t)n * 512 + kk + 1];
            }
            r[nf * 2 + h] = h2u(__floats2half2_rn(v0, v1));
        }
    }
    g_wf[((size_t)(ks * 4 + wc) * 2 + 0) * 32 + lane] = make_uint4(r[0], r[1], r[2], r[3]);
    g_wf[((size_t)(ks * 4 + wc) * 2 + 1) * 32 + lane] = make_uint4(r[4], r[5], r[6], r[7]);
}

// ---------------------------------------------------------------------------
// enc prep: transpose x -> g_enc[i][b] codes + g_xh fp16 copy.
// grid (128, 16), block 256. Tile: 64 b-rows x 32 features.
// ---------------------------------------------------------------------------
__global__ __launch_bounds__(256)
void kan_enc(const float* __restrict__ x)
{
    __shared__ uint2 se[32][65];    // [i_local][b_local], padded
    const int b0 = blockIdx.x * 64;
    const int i0 = blockIdx.y * 32;
    const int t  = threadIdx.x;
    const int row = t >> 2;         // 0..63
    const int seg = t & 3;          // 8 features each

    const float* xp = x + (size_t)(b0 + row) * 512 + i0 + seg * 8;
    float4 v0 = *reinterpret_cast<const float4*>(xp);
    float4 v1 = *reinterpret_cast<const float4*>(xp + 4);
    float xv[8] = {v0.x, v0.y, v0.z, v0.w, v1.x, v1.y, v1.z, v1.w};

    // fp16 copy (row-major, coalesced)
    uint4 hx = make_uint4(h2u(__floats2half2_rn(xv[0], xv[1])),
                          h2u(__floats2half2_rn(xv[2], xv[3])),
                          h2u(__floats2half2_rn(xv[4], xv[5])),
                          h2u(__floats2half2_rn(xv[6], xv[7])));
    *reinterpret_cast<uint4*>(g_xh + (size_t)(b0 + row) * 512 + i0 + seg * 8) = hx;

    #pragma unroll
    for (int k = 0; k < 8; k++) {
        float p = fminf(fmaxf((xv[k] - X_MIN_F) * SCALE_F, 0.0f), 15.0f);
        int   k0 = min((int)p, 14);
        float f  = p - (float)k0;
        uint32_t fh = (uint32_t)__half_as_ushort(__float2half_rn(f));
        uint32_t mh = (uint32_t)__half_as_ushort(__float2half_rn(1.0f - f));
        se[seg * 8 + k][row] = make_uint2((fh << 16) | mh, (uint32_t)k0);
    }
    __syncthreads();

    // write transposed: thread covers (i_local = t>>3, 8 b's at (t&7)*8)
    const int il = t >> 3, ch = t & 7;
    uint4* dst = reinterpret_cast<uint4*>(g_enc + (size_t)(i0 + il) * 8192 + b0 + ch * 8);
    #pragma unroll
    for (int m = 0; m < 4; m++) {
        uint2 a = se[il][ch * 8 + m * 2];
        uint2 b = se[il][ch * 8 + m * 2 + 1];
        dst[m] = make_uint4(a.x, a.y, b.x, b.y);
    }
}

// ---------------------------------------------------------------------------
// Main GEMM: grid (64, 2), block 256. CTA = 128 rows x 128 outs x K'/2.
// Warp grid 2(M) x 4(N), warp tile 64x32. ZERO SMEM: A fragments built in
// registers from enc codes (spline) / g_xh (skip); B via depth-paired LDG.
// ---------------------------------------------------------------------------
__global__ __launch_bounds__(256)
void kan_mma()
{
    const int tid  = threadIdx.x;
    const int lane = tid & 31;
    const int w    = tid >> 5;
    const int wm   = w >> 2;            // 0..1 (64 rows)
    const int wc   = w & 3;             // 0..3 (32 outs)
    const int bt   = blockIdx.x;        // 0..63
    const int ksp  = blockIdx.y;        // 0..1
    const int rb0  = bt * 128 + wm * 64;

    float acc[4][4][4];
    #pragma unroll
    for (int p = 0; p < 4; p++)
        #pragma unroll
        for (int nf = 0; nf < 4; nf++)
            #pragma unroll
            for (int v = 0; v < 4; v++) acc[p][nf][v] = 0.0f;

    const int      c0    = (lane & 3) * 2;
    const uint32_t cA16  = (uint32_t)((c0 + 1) * 16);
    const uint2*   ebase = g_enc + rb0 + (lane >> 2);
    const char*    gwb   = reinterpret_cast<const char*>(g_wf);
    const uint32_t bwoff = (uint32_t)(wc * 1024 + lane * 16);

    auto ldE = [&](int ks, uint2* e) {
        const uint2* ep = ebase + (size_t)ks * 8192;
        #pragma unroll
        for (int p = 0; p < 4; p++) {
            e[p * 2]     = __ldg(ep + p * 16);
            e[p * 2 + 1] = __ldg(ep + p * 16 + 8);
        }
    };
    auto ldB = [&](int ks, uint4& q0, uint4& q1) {
        const uint4* bp = reinterpret_cast<const uint4*>(gwb + (size_t)ks * 4096 + bwoff);
        q0 = __ldg(bp);
        q1 = __ldg(bp + 32);
    };
    // Build A fragments for one m-frag pair from 2 enc codes.
    // hat pair at cols (c, c+1): s = 16(c+1) - 16*k0; s in {0,16,32} hits,
    // value = funnelshift of (f<<16|onemf); else 0.  (identical halves to R12)
    auto step = [&](const uint2* e, const uint4& q0, const uint4& q1) {
        #pragma unroll
        for (int p = 0; p < 4; p++) {
            uint32_t a[4];
            #pragma unroll
            for (int j = 0; j < 2; j++) {
                const uint32_t lo  = e[p * 2 + j].x;
                const uint32_t k16 = e[p * 2 + j].y << 4;
                const uint32_t rlo = lo << 16, rhi = lo >> 16;
                const uint32_t sA  = cA16 - k16;
                const uint32_t sB  = sA + 128;
                a[j]     = (sA <= 32u) ? __funnelshift_rc(rlo, rhi, sA) : 0u;
                a[j + 2] = (sB <= 32u) ? __funnelshift_rc(rlo, rhi, sB) : 0u;
            }
            mma16816(acc[p][0], a, q0.x, q0.y);
            mma16816(acc[p][1], a, q0.z, q0.w);
            mma16816(acc[p][2], a, q1.x, q1.y);
            mma16816(acc[p][3], a, q1.z, q1.w);
        }
    };

    // ---- spline phase ----
    const int ks0 = ksp ? 272 : 0;
    const int ks1 = ksp ? 512 : 272;
    {
        uint2 e0[8], e1[8];
        uint4 q00, q01, q10, q11;
        ldE(ks0, e0);     ldB(ks0, q00, q01);
        ldE(ks0 + 1, e1); ldB(ks0 + 1, q10, q11);
        for (int ks = ks0; ks < ks1; ks += 2) {
            step(e0, q00, q01);
            if (ks + 2 < ks1) { ldE(ks + 2, e0); ldB(ks + 2, q00, q01); }
            step(e1, q10, q11);
            if (ks + 3 < ks1) { ldE(ks + 3, e1); ldB(ks + 3, q10, q11); }
        }
    }

    // ---- skip phase (ksp == 1 only): A = fp16 x values ----
    if (ksp == 1) {
        auto ldX = [&](int ks, uint32_t* ax) {
            const __half* base = g_xh + (size_t)(rb0 + (lane >> 2)) * 512
                               + (ks * 16 - 8192) + c0;
            #pragma unroll
            for (int p = 0; p < 4; p++)
                #pragma unroll
                for (int j = 0; j < 2; j++) {
                    const __half* rp = base + (size_t)(p * 16 + j * 8) * 512;
                    ax[p * 4 + j]     = __ldg(reinterpret_cast<const uint32_t*>(rp));
                    ax[p * 4 + j + 2] = __ldg(reinterpret_cast<const uint32_t*>(rp + 8));
                }
        };
        auto stepx = [&](const uint32_t* ax, const uint4& q0, const uint4& q1) {
            #pragma unroll
            for (int p = 0; p < 4; p++) {
                const uint32_t* a = ax + p * 4;
                mma16816(acc[p][0], a, q0.x, q0.y);
                mma16816(acc[p][1], a, q0.z, q0.w);
                mma16816(acc[p][2], a, q1.x, q1.y);
                mma16816(acc[p][3], a, q1.z, q1.w);
            }
        };
        uint32_t ax0[16], ax1[16];
        uint4 q00, q01, q10, q11;
        ldX(512, ax0); ldB(512, q00, q01);
        ldX(513, ax1); ldB(513, q10, q11);
        for (int ks = 512; ks < 544; ks += 2) {
            stepx(ax0, q00, q01);
            if (ks + 2 < 544) { ldX(ks + 2, ax0); ldB(ks + 2, q00, q01); }
            stepx(ax1, q10, q11);
            if (ks + 3 < 544) { ldX(ks + 3, ax1); ldB(ks + 3, q10, q11); }
        }
    }

    // Epilogue: fp32 partials (layout identical to R12).
    float* yb = g_part + (size_t)ksp * (B_SZ * D_OUT) + (size_t)rb0 * 128;
    #pragma unroll
    for (int p = 0; p < 4; p++) {
        const int r0 = p * 16 + (lane >> 2);
        #pragma unroll
        for (int nf = 0; nf < 4; nf++) {
            const int n0 = wc * 32 + nf * 8 + (lane & 3) * 2;
            *reinterpret_cast<float2*>(yb + (size_t)r0 * 128 + n0) =
                make_float2(acc[p][nf][0], acc[p][nf][1]);
            *reinterpret_cast<float2*>(yb + (size_t)(r0 + 8) * 128 + n0) =
                make_float2(acc[p][nf][2], acc[p][nf][3]);
        }
    }
}

// ---------------------------------------------------------------------------
// Reduce: y = part0 + part1 + bias. grid=1024, block=256, float4/thread.
// ---------------------------------------------------------------------------
__global__ __launch_bounds__(256)
void kan_reduce(const float* __restrict__ bias, float* __restrict__ y)
{
    const int t = blockIdx.x * 256 + threadIdx.x;
    float4 a  = reinterpret_cast<const float4*>(g_part)[t];
    float4 b  = reinterpret_cast<const float4*>(g_part)[t + (B_SZ * D_OUT / 4)];
    float4 bi = reinterpret_cast<const float4*>(bias)[t & 31];
    reinterpret_cast<float4*>(y)[t] =
        make_float4(a.x + b.x + bi.x, a.y + b.y + bi.y,
                    a.z + b.z + bi.z, a.w + b.w + bi.w);
}

// ---------------------------------------------------------------------------
// kernel_launch: inputs per metadata order: x, weights, skip_w, bias
// ---------------------------------------------------------------------------
extern "C" void kernel_launch(void* const* d_in, const int* in_sizes, int n_in,
                              void* d_out, int out_size)
{
    const float* x    = (const float*)d_in[0];
    const float* w    = (const float*)d_in[1];
    const float* skip = (const float*)d_in[2];
    const float* bias = (const float*)d_in[3];
    float* y = (float*)d_out;

    kan_wprep<<<dim3(136, 4), 128>>>(w, skip);
    kan_enc<<<dim3(128, 16), 256>>>(x);
    kan_mma<<<dim3(64, 2), 256>>>();
    kan_reduce<<<(B_SZ * D_OUT / 4) / 256, 256>>>(bias, y);
}

// round 14
// speedup vs baseline: 1.7539x; 1.7539x over previous
#include <cuda_runtime.h>
#include <cuda_fp16.h>
#include <cstdint>

// Shapes (fixed for KANLayer_17265768530645)
#define B_SZ    8192
#define D_IN    512
#define D_OUT   128
#define X_MIN_F (-3.0f)
#define DENOM   6.00000001f
#define SCALE_F (15.0f / DENOM)

// GEMM: y[b,n] = sum_{k'} C[b,k'] * W'[n,k'],  K' = 8704
#define KSTEPS   544          // K'/16
#define NCHUNK   68           // K'/128
#define KHALF    34           // chunks per K-split

// W' as mma B-fragments, CHUNK-MAJOR (32KB per 128-k chunk).
__device__ __align__(128) uint4 g_wf[KSTEPS * 4 * 2 * 32];          // 2.2 MB
// K-split partial outputs: [2][B][128] fp32
__device__ __align__(16)  float g_part[2 * (size_t)B_SZ * D_OUT];   // 8.4 MB

// ---------------- PTX helpers ----------------------------------------------
__device__ __forceinline__ void ldm4(uint32_t* a, uint32_t addr) {
    asm volatile("ldmatrix.sync.aligned.m8n8.x4.shared.b16 {%0,%1,%2,%3}, [%4];"
                 : "=r"(a[0]), "=r"(a[1]), "=r"(a[2]), "=r"(a[3]) : "r"(addr));
}
__device__ __forceinline__ void mma16816(float* c, const uint32_t* a,
                                         uint32_t b0, uint32_t b1) {
    asm volatile(
        "mma.sync.aligned.m16n8k16.row.col.f32.f16.f16.f32 "
        "{%0,%1,%2,%3}, {%4,%5,%6,%7}, {%8,%9}, {%0,%1,%2,%3};"
        : "+f"(c[0]), "+f"(c[1]), "+f"(c[2]), "+f"(c[3])
        : "r"(a[0]), "r"(a[1]), "r"(a[2]), "r"(a[3]), "r"(b0), "r"(b1));
}
__device__ __forceinline__ uint32_t h2u(__half2 h) {
    return *reinterpret_cast<uint32_t*>(&h);
}
__device__ __forceinline__ void cp16(uint32_t saddr, const void* g) {
    asm volatile("cp.async.ca.shared.global [%0], [%1], 16;"
                 :: "r"(saddr), "l"(g));
}
#define CP_COMMIT() asm volatile("cp.async.commit_group;" ::: "memory")
#define CP_WAIT0()  asm volatile("cp.async.wait_group 0;"  ::: "memory")

// ---------------------------------------------------------------------------
// W' prep (validated R7-R12, unchanged).
// ---------------------------------------------------------------------------
__global__ void kan_wprep(const float* __restrict__ w,    // (128, 512, 16)
                          const float* __restrict__ s)    // (128, 512)
{
    const int wc   = blockIdx.y;
    const int lane = threadIdx.x & 31;
    const int ks   = blockIdx.x * 4 + (threadIdx.x >> 5);

    uint32_t r[8];
    #pragma unroll
    for (int nf = 0; nf < 4; nf++) {
        const int n = wc * 32 + nf * 8 + (lane >> 2);
        #pragma unroll
        for (int h = 0; h < 2; h++) {
            const int k = ks * 16 + (lane & 3) * 2 + h * 8;
            float v0, v1;
            if (ks < 512) {
                v0 = w[(size_t)n * 8192 + k];
                v1 = w[(size_t)n * 8192 + k + 1];
            } else {
                const int kk = k - 8192;
                v0 = s[(size_t)n * 512 + kk];
                v1 = s[(size_t)n * 512 + kk + 1];
            }
            r[nf * 2 + h] = h2u(__floats2half2_rn(v0, v1));
        }
    }
    g_wf[((size_t)(ks * 4 + wc) * 2 + 0) * 32 + lane] = make_uint4(r[0], r[1], r[2], r[3]);
    g_wf[((size_t)(ks * 4 + wc) * 2 + 1) * 32 + lane] = make_uint4(r[4], r[5], r[6], r[7]);
}

// ---------------------------------------------------------------------------
// C-chunk builders (128-row tile). Thread: bb = tid>>1 (row), il0 = (tid&1)*4.
// Swizzle (bank-correct): byte(b, cb) = b*256 + (cb ^ ((b&7)<<4)).
// ---------------------------------------------------------------------------
__device__ __forceinline__ void build_spline4(char* rb, uint32_t swb,
                                              float4 xv, int il0)
{
    float xs[4] = {xv.x, xv.y, xv.z, xv.w};
    #pragma unroll
    for (int e = 0; e < 4; e++) {
        const int il = il0 + e;
        float p = fminf(fmaxf((xs[e] - X_MIN_F) * SCALE_F, 0.0f), 15.0f);
        int   k0 = min((int)p, 14);
        float f  = p - (float)k0;
        *reinterpret_cast<uint4*>(rb + ((uint32_t)(il * 32)      ^ swb)) = make_uint4(0,0,0,0);
        *reinterpret_cast<uint4*>(rb + ((uint32_t)(il * 32 + 16) ^ swb)) = make_uint4(0,0,0,0);
        const uint32_t cb = (uint32_t)(il * 32 + k0 * 2);
        *reinterpret_cast<__half*>(rb + (cb ^ swb))       = __float2half_rn(1.0f - f);
        *reinterpret_cast<__half*>(rb + ((cb + 2) ^ swb)) = __float2half_rn(f);
    }
}

__device__ __forceinline__ void build_skip4(char* rb, uint32_t swb,
                                            const float* __restrict__ xp, int il0)
{
    #pragma unroll
    for (int v = 0; v < 8; v++) {
        float4 f0 = *reinterpret_cast<const float4*>(xp + v * 8);
        float4 f1 = *reinterpret_cast<const float4*>(xp + v * 8 + 4);
        uint4 pk = make_uint4(h2u(__floats2half2_rn(f0.x, f0.y)),
                              h2u(__floats2half2_rn(f0.z, f0.w)),
                              h2u(__floats2half2_rn(f1.x, f1.y)),
                              h2u(__floats2half2_rn(f1.z, f1.w)));
        *reinterpret_cast<uint4*>(rb + ((uint32_t)(il0 * 32 + v * 16) ^ swb)) = pk;
    }
}

// ---------------------------------------------------------------------------
// Main GEMM: grid (64, 2), block 256. CTA = 128 rows x 128 outs x K'/2.
// Warp grid 2(M) x 4(N), warp tile 64x32. B cp.async-staged one chunk ahead;
// C double-buffered. Swizzle bits 4-6 (bank-visible) -> conflict-free LDSM.
// ---------------------------------------------------------------------------
__global__ __launch_bounds__(256)
void kan_mma(const float* __restrict__ x)
{
    extern __shared__ __align__(128) char dsm[];
    char* cs  = dsm;                    // 2 x 32768 (C: 128 rows x 256B)
    char* bsm = dsm + 65536;            // 2 x 32768 (B chunks)

    const int tid  = threadIdx.x;
    const int lane = tid & 31;
    const int w    = tid >> 5;
    const int wm   = w >> 2;            // 0..1  (64 rows each)
    const int wc   = w & 3;             // 0..3  (32 outs each)
    const int bt   = blockIdx.x;        // b-tile 0..63 (128 rows each)
    const int ksp  = blockIdx.y;        // K-split 0..1
    const int ch0  = ksp * KHALF;

    float acc[4][4][4];                 // [A-frag p][n-frag][4]
    #pragma unroll
    for (int p = 0; p < 4; p++)
        #pragma unroll
        for (int nf = 0; nf < 4; nf++)
            #pragma unroll
            for (int v = 0; v < 4; v++)
                acc[p][nf][v] = 0.0f;

    const uint32_t cs32 = (uint32_t)__cvta_generic_to_shared(cs);
    const uint32_t bs32 = (uint32_t)__cvta_generic_to_shared(bsm);
    // Bank-correct swizzle: XOR bits 4-6 with (row&7).
    const uint32_t swz    = (uint32_t)((lane & 7) << 4);
    const uint32_t achunk = (uint32_t)((lane >> 4) << 4);
    // Row part of A address (chunk part XORed per k-step below).
    const uint32_t arowoff = (uint32_t)((wm * 64 + (lane & 15)) * 256);

    const int bb  = tid >> 1;           // 0..127 (C row)
    const int il0 = (tid & 1) * 4;      // 4 i-slots per thread
    const uint32_t swb = (uint32_t)((bb & 7) << 4);
    const float* xrow = x + (size_t)(bt * 128 + bb) * 512;

    const uint32_t bwoff = (uint32_t)(wc * 1024 + lane * 16);

    const char* gwb = reinterpret_cast<const char*>(g_wf);
    auto issue_copy = [&](int ch, int buf) {
        const char* src = gwb + (size_t)ch * 32768 + tid * 16;
        uint32_t dst = bs32 + (uint32_t)buf * 32768 + (uint32_t)(tid * 16);
        #pragma unroll
        for (int j = 0; j < 8; j++)
            cp16(dst + j * 4096, src + j * 4096);
        CP_COMMIT();
    };

    // Prologue: stage B chunk ch0, build C chunk ch0 (ch0 < 64: spline).
    issue_copy(ch0, 0);
    {
        float4 xv = *reinterpret_cast<const float4*>(xrow + ch0 * 8 + il0);
        build_spline4(cs + bb * 256, swb, xv, il0);
    }
    CP_WAIT0();
    __syncthreads();

    for (int cl = 0; cl < KHALF; cl++) {
        const int ch  = ch0 + cl;
        const int cur = cl & 1, nxt = cur ^ 1;

        if (cl + 1 < KHALF) issue_copy(ch + 1, nxt);

        float4 xpre = make_float4(0.f, 0.f, 0.f, 0.f);
        const bool haveNext  = (cl + 1 < KHALF);
        const bool nextSplin = (ch + 1 < 64);
        if (haveNext && nextSplin)
            xpre = *reinterpret_cast<const float4*>(xrow + (ch + 1) * 8 + il0);

        const uint32_t abase = cs32 + (uint32_t)cur * 32768 + arowoff;
        const char* bchunk = bsm + cur * 32768;

        // Depth-1 k-step pipeline over SMEM-resident B.
        uint4 q0 = *reinterpret_cast<const uint4*>(bchunk + bwoff);
        uint4 q1 = *reinterpret_cast<const uint4*>(bchunk + bwoff + 512);

        #pragma unroll
        for (int ksl = 0; ksl < 8; ksl++) {
            const uint4 r0 = q0, r1 = q1;
            if (ksl + 1 < 8) {
                q0 = *reinterpret_cast<const uint4*>(bchunk + (ksl + 1) * 4096 + bwoff);
                q1 = *reinterpret_cast<const uint4*>(bchunk + (ksl + 1) * 4096 + bwoff + 512);
            }
            // Combined chunk offset XORed with the bank swizzle (bit 4 included).
            const uint32_t koff = (achunk + (uint32_t)(ksl * 32)) ^ swz;

            #pragma unroll
            for (int p = 0; p < 4; p++) {
                uint32_t a[4];
                ldm4(a, abase + (uint32_t)p * 4096 + koff);
                mma16816(acc[p][0], a, r0.x, r0.y);
                mma16816(acc[p][1], a, r0.z, r0.w);
                mma16816(acc[p][2], a, r1.x, r1.y);
                mma16816(acc[p][3], a, r1.z, r1.w);
            }
        }

        if (haveNext) {
            char* rb = cs + nxt * 32768 + bb * 256;
            if (nextSplin) {
                build_spline4(rb, swb, xpre, il0);
            } else {
                build_skip4(rb, swb, xrow + (ch + 1 - 64) * 128 + il0 * 16, il0);
            }
        }
        CP_WAIT0();
        __syncthreads();
    }

    // Epilogue: fp32 partials.
    float* yb = g_part + (size_t)ksp * (B_SZ * D_OUT)
                       + (size_t)(bt * 128 + wm * 64) * 128;
    #pragma unroll
    for (int p = 0; p < 4; p++) {
        const int r0 = p * 16 + (lane >> 2);
        #pragma unroll
        for (int nf = 0; nf < 4; nf++) {
            const int n0 = wc * 32 + nf * 8 + (lane & 3) * 2;
            *reinterpret_cast<float2*>(yb + (size_t)r0 * 128 + n0) =
                make_float2(acc[p][nf][0], acc[p][nf][1]);
            *reinterpret_cast<float2*>(yb + (size_t)(r0 + 8) * 128 + n0) =
                make_float2(acc[p][nf][2], acc[p][nf][3]);
        }
    }
}

// ---------------------------------------------------------------------------
// Reduce: y = part0 + part1 + bias. grid=1024, block=256, float4/thread.
// ---------------------------------------------------------------------------
__global__ __launch_bounds__(256)
void kan_reduce(const float* __restrict__ bias, float* __restrict__ y)
{
    const int t = blockIdx.x * 256 + threadIdx.x;      // over B*128/4
    float4 a  = reinterpret_cast<const float4*>(g_part)[t];
    float4 b  = reinterpret_cast<const float4*>(g_part)[t + (B_SZ * D_OUT / 4)];
    float4 bi = reinterpret_cast<const float4*>(bias)[t & 31];
    reinterpret_cast<float4*>(y)[t] =
        make_float4(a.x + b.x + bi.x, a.y + b.y + bi.y,
                    a.z + b.z + bi.z, a.w + b.w + bi.w);
}

// ---------------------------------------------------------------------------
// kernel_launch: inputs per metadata order: x, weights, skip_w, bias
// ---------------------------------------------------------------------------
#define SMEM_DYN (128 * 1024)

extern "C" void kernel_launch(void* const* d_in, const int* in_sizes, int n_in,
                              void* d_out, int out_size)
{
    const float* x    = (const float*)d_in[0];
    const float* w    = (const float*)d_in[1];
    const float* skip = (const float*)d_in[2];
    const float* bias = (const float*)d_in[3];
    float* y = (float*)d_out;

    cudaFuncSetAttribute(kan_mma, cudaFuncAttributeMaxDynamicSharedMemorySize,
                         SMEM_DYN);
    kan_wprep<<<dim3(136, 4), 128>>>(w, skip);
    kan_mma<<<dim3(64, 2), 256, SMEM_DYN>>>(x);
    kan_reduce<<<(B_SZ * D_OUT / 4) / 256, 256>>>(bias, y);
}

// round 15
// speedup vs baseline: 1.7554x; 1.0008x over previous
#include <cuda_runtime.h>
#include <cuda_fp16.h>
#include <cstdint>

// Shapes (fixed for KANLayer_17265768530645)
#define B_SZ    8192
#define D_IN    512
#define D_OUT   128
#define X_MIN_F (-3.0f)
#define DENOM   6.00000001f
#define SCALE_F (15.0f / DENOM)

// GEMM: y[b,n] = sum_{k'} C[b,k'] * W'[n,k'],  K' = 8704
#define KSTEPS   544          // K'/16
#define NCHUNK   68           // K'/128
#define KHALF    34           // chunks per K-split

// W' as mma B-fragments, CHUNK-MAJOR (4KB per kstep: ((ks*4+wc)*2+h)*32+lane).
__device__ __align__(128) uint4 g_wf[KSTEPS * 4 * 2 * 32];          // 2.2 MB
// K-split partial outputs: [2][B][128] fp32
__device__ __align__(16)  float g_part[2 * (size_t)B_SZ * D_OUT];   // 8.4 MB

// ---------------- PTX helpers ----------------------------------------------
__device__ __forceinline__ void ldm4(uint32_t* a, uint32_t addr) {
    asm volatile("ldmatrix.sync.aligned.m8n8.x4.shared.b16 {%0,%1,%2,%3}, [%4];"
                 : "=r"(a[0]), "=r"(a[1]), "=r"(a[2]), "=r"(a[3]) : "r"(addr));
}
__device__ __forceinline__ void mma16816(float* c, const uint32_t* a,
                                         uint32_t b0, uint32_t b1) {
    asm volatile(
        "mma.sync.aligned.m16n8k16.row.col.f32.f16.f16.f32 "
        "{%0,%1,%2,%3}, {%4,%5,%6,%7}, {%8,%9}, {%0,%1,%2,%3};"
        : "+f"(c[0]), "+f"(c[1]), "+f"(c[2]), "+f"(c[3])
        : "r"(a[0]), "r"(a[1]), "r"(a[2]), "r"(a[3]), "r"(b0), "r"(b1));
}
__device__ __forceinline__ uint32_t h2u(__half2 h) {
    return *reinterpret_cast<uint32_t*>(&h);
}

// ---------------------------------------------------------------------------
// W' prep (validated R7-R14, unchanged).
// ---------------------------------------------------------------------------
__global__ void kan_wprep(const float* __restrict__ w,    // (128, 512, 16)
                          const float* __restrict__ s)    // (128, 512)
{
    const int wc   = blockIdx.y;
    const int lane = threadIdx.x & 31;
    const int ks   = blockIdx.x * 4 + (threadIdx.x >> 5);

    uint32_t r[8];
    #pragma unroll
    for (int nf = 0; nf < 4; nf++) {
        const int n = wc * 32 + nf * 8 + (lane >> 2);
        #pragma unroll
        for (int h = 0; h < 2; h++) {
            const int k = ks * 16 + (lane & 3) * 2 + h * 8;
            float v0, v1;
            if (ks < 512) {
                v0 = w[(size_t)n * 8192 + k];
                v1 = w[(size_t)n * 8192 + k + 1];
            } else {
                const int kk = k - 8192;
                v0 = s[(size_t)n * 512 + kk];
                v1 = s[(size_t)n * 512 + kk + 1];
            }
            r[nf * 2 + h] = h2u(__floats2half2_rn(v0, v1));
        }
    }
    g_wf[((size_t)(ks * 4 + wc) * 2 + 0) * 32 + lane] = make_uint4(r[0], r[1], r[2], r[3]);
    g_wf[((size_t)(ks * 4 + wc) * 2 + 1) * 32 + lane] = make_uint4(r[4], r[5], r[6], r[7]);
}

// ---------------------------------------------------------------------------
// C-chunk builders (128-row tile). Thread: bb = tid>>1 (row), il0 = (tid&1)*4.
// Bank-correct swizzle: byte(b, cb) = b*256 + (cb ^ ((b&7)<<4)).
// ---------------------------------------------------------------------------
__device__ __forceinline__ void build_spline4(char* rb, uint32_t swb,
                                              float4 xv, int il0)
{
    float xs[4] = {xv.x, xv.y, xv.z, xv.w};
    #pragma unroll
    for (int e = 0; e < 4; e++) {
        const int il = il0 + e;
        float p = fminf(fmaxf((xs[e] - X_MIN_F) * SCALE_F, 0.0f), 15.0f);
        int   k0 = min((int)p, 14);
        float f  = p - (float)k0;
        *reinterpret_cast<uint4*>(rb + ((uint32_t)(il * 32)      ^ swb)) = make_uint4(0,0,0,0);
        *reinterpret_cast<uint4*>(rb + ((uint32_t)(il * 32 + 16) ^ swb)) = make_uint4(0,0,0,0);
        const uint32_t cb = (uint32_t)(il * 32 + k0 * 2);
        *reinterpret_cast<__half*>(rb + (cb ^ swb))       = __float2half_rn(1.0f - f);
        *reinterpret_cast<__half*>(rb + ((cb + 2) ^ swb)) = __float2half_rn(f);
    }
}

__device__ __forceinline__ void build_skip4(char* rb, uint32_t swb,
                                            const float* __restrict__ xp, int il0)
{
    #pragma unroll
    for (int v = 0; v < 8; v++) {
        float4 f0 = *reinterpret_cast<const float4*>(xp + v * 8);
        float4 f1 = *reinterpret_cast<const float4*>(xp + v * 8 + 4);
        uint4 pk = make_uint4(h2u(__floats2half2_rn(f0.x, f0.y)),
                              h2u(__floats2half2_rn(f0.z, f0.w)),
                              h2u(__floats2half2_rn(f1.x, f1.y)),
                              h2u(__floats2half2_rn(f1.z, f1.w)));
        *reinterpret_cast<uint4*>(rb + ((uint32_t)(il0 * 32 + v * 16) ^ swb)) = pk;
    }
}

// ---------------------------------------------------------------------------
// Main GEMM: grid (64, 2), block 256, 2 CTAs/SM. CTA = 128 rows x 128 outs x
// K'/2. Warp grid 2(M) x 4(N), warp tile 64x32. C double-buffered in SMEM
// (64KB total); B via direct L2 LDG with a depth-2 register ring (no SMEM).
// ---------------------------------------------------------------------------
__global__ __launch_bounds__(256, 2)
void kan_mma(const float* __restrict__ x)
{
    extern __shared__ __align__(128) char dsm[];
    char* cs = dsm;                     // 2 x 32768 (C: 128 rows x 256B)

    const int tid  = threadIdx.x;
    const int lane = tid & 31;
    const int w    = tid >> 5;
    const int wm   = w >> 2;            // 0..1  (64 rows each)
    const int wc   = w & 3;             // 0..3  (32 outs each)
    const int bt   = blockIdx.x;        // b-tile 0..63 (128 rows each)
    const int ksp  = blockIdx.y;        // K-split 0..1
    const int ch0  = ksp * KHALF;
    const int kse  = (ch0 + KHALF) * 8; // kstep end

    float acc[4][4][4];                 // [A-frag p][n-frag][4]
    #pragma unroll
    for (int p = 0; p < 4; p++)
        #pragma unroll
        for (int nf = 0; nf < 4; nf++)
            #pragma unroll
            for (int v = 0; v < 4; v++)
                acc[p][nf][v] = 0.0f;

    const uint32_t cs32 = (uint32_t)__cvta_generic_to_shared(cs);
    const uint32_t swz    = (uint32_t)((lane & 7) << 4);
    const uint32_t achunk = (uint32_t)((lane >> 4) << 4);
    const uint32_t arowoff = (uint32_t)((wm * 64 + (lane & 15)) * 256);

    const int bb  = tid >> 1;           // 0..127 (C row)
    const int il0 = (tid & 1) * 4;      // 4 i-slots per thread
    const uint32_t swb = (uint32_t)((bb & 7) << 4);
    const float* xrow = x + (size_t)(bt * 128 + bb) * 512;

    // B fragment stream (direct from L2-resident g_wf).
    const char* gwb = reinterpret_cast<const char*>(g_wf);
    const uint32_t bwoff = (uint32_t)(wc * 1024 + lane * 16);
    auto ldB = [&](int ks, uint4& q0, uint4& q1) {
        const uint4* bp = reinterpret_cast<const uint4*>(gwb + (size_t)ks * 4096 + bwoff);
        q0 = __ldg(bp);
        q1 = __ldg(bp + 32);
    };

    // Depth-2 B register ring: slot ks&1 holds kstep ks.
    uint4 bq[2][2];
    ldB(ch0 * 8,     bq[0][0], bq[0][1]);
    ldB(ch0 * 8 + 1, bq[1][0], bq[1][1]);

    // Build C chunk ch0 (ch0 < 64: spline).
    {
        float4 xv = *reinterpret_cast<const float4*>(xrow + ch0 * 8 + il0);
        build_spline4(cs + bb * 256, swb, xv, il0);
    }
    __syncthreads();

    for (int cl = 0; cl < KHALF; cl++) {
        const int ch  = ch0 + cl;
        const int cur = cl & 1, nxt = cur ^ 1;

        float4 xpre = make_float4(0.f, 0.f, 0.f, 0.f);
        const bool haveNext  = (cl + 1 < KHALF);
        const bool nextSplin = (ch + 1 < 64);
        if (haveNext && nextSplin)
            xpre = *reinterpret_cast<const float4*>(xrow + (ch + 1) * 8 + il0);

        const uint32_t abase = cs32 + (uint32_t)cur * 32768 + arowoff;

        #pragma unroll
        for (int ksl = 0; ksl < 8; ksl++) {
            const int ks = ch * 8 + ksl;
            const int slot = ks & 1;
            const uint4 r0 = bq[slot][0];
            const uint4 r1 = bq[slot][1];
            if (ks + 2 < kse) ldB(ks + 2, bq[slot][0], bq[slot][1]);

            const uint32_t koff = (achunk + (uint32_t)(ksl * 32)) ^ swz;

            #pragma unroll
            for (int p = 0; p < 4; p++) {
                uint32_t a[4];
                ldm4(a, abase + (uint32_t)p * 4096 + koff);
                mma16816(acc[p][0], a, r0.x, r0.y);
                mma16816(acc[p][1], a, r0.z, r0.w);
                mma16816(acc[p][2], a, r1.x, r1.y);
                mma16816(acc[p][3], a, r1.z, r1.w);
            }
        }

        if (haveNext) {
            char* rb = cs + nxt * 32768 + bb * 256;
            if (nextSplin) {
                build_spline4(rb, swb, xpre, il0);
            } else {
                build_skip4(rb, swb, xrow + (ch + 1 - 64) * 128 + il0 * 16, il0);
            }
        }
        __syncthreads();
    }

    // Epilogue: fp32 partials.
    float* yb = g_part + (size_t)ksp * (B_SZ * D_OUT)
                       + (size_t)(bt * 128 + wm * 64) * 128;
    #pragma unroll
    for (int p = 0; p < 4; p++) {
        const int r0 = p * 16 + (lane >> 2);
        #pragma unroll
        for (int nf = 0; nf < 4; nf++) {
            const int n0 = wc * 32 + nf * 8 + (lane & 3) * 2;
            *reinterpret_cast<float2*>(yb + (size_t)r0 * 128 + n0) =
                make_float2(acc[p][nf][0], acc[p][nf][1]);
            *reinterpret_cast<float2*>(yb + (size_t)(r0 + 8) * 128 + n0) =
                make_float2(acc[p][nf][2], acc[p][nf][3]);
        }
    }
}

// ---------------------------------------------------------------------------
// Reduce: y = part0 + part1 + bias. grid=1024, block=256, float4/thread.
// ---------------------------------------------------------------------------
__global__ __launch_bounds__(256)
void kan_reduce(const float* __restrict__ bias, float* __restrict__ y)
{
    const int t = blockIdx.x * 256 + threadIdx.x;      // over B*128/4
    float4 a  = reinterpret_cast<const float4*>(g_part)[t];
    float4 b  = reinterpret_cast<const float4*>(g_part)[t + (B_SZ * D_OUT / 4)];
    float4 bi = reinterpret_cast<const float4*>(bias)[t & 31];
    reinterpret_cast<float4*>(y)[t] =
        make_float4(a.x + b.x + bi.x, a.y + b.y + bi.y,
                    a.z + b.z + bi.z, a.w + b.w + bi.w);
}

// ---------------------------------------------------------------------------
// kernel_launch: inputs per metadata order: x, weights, skip_w, bias
// ---------------------------------------------------------------------------
#define SMEM_DYN (64 * 1024)

extern "C" void kernel_launch(void* const* d_in, const int* in_sizes, int n_in,
                              void* d_out, int out_size)
{
    const float* x    = (const float*)d_in[0];
    const float* w    = (const float*)d_in[1];
    const float* skip = (const float*)d_in[2];
    const float* bias = (const float*)d_in[3];
    float* y = (float*)d_out;

    cudaFuncSetAttribute(kan_mma, cudaFuncAttributeMaxDynamicSharedMemorySize,
                         SMEM_DYN);
    kan_wprep<<<dim3(136, 4), 128>>>(w, skip);
    kan_mma<<<dim3(64, 2), 256, SMEM_DYN>>>(x);
    kan_reduce<<<(B_SZ * D_OUT / 4) / 256, 256>>>(bias, y);
}

// round 16
// speedup vs baseline: 1.8061x; 1.0289x over previous
#include <cuda_runtime.h>
#include <cuda_fp16.h>
#include <cstdint>

// Shapes (fixed for KANLayer_17265768530645)
#define B_SZ    8192
#define D_IN    512
#define D_OUT   128
#define X_MIN_F (-3.0f)
#define DENOM   6.00000001f
#define SCALE_F (15.0f / DENOM)

// GEMM: y[b,n] = sum_{k'} C[b,k'] * W'[n,k'],  K' = 8704
#define KSTEPS   544          // K'/16
#define NCHUNK   68           // K'/128
#define NSPLIT   4            // K-splits
#define KPART    17           // chunks per K-split

// W' as mma B-fragments, CHUNK-MAJOR (4KB per kstep: ((ks*4+wc)*2+h)*32+lane).
__device__ __align__(128) uint4 g_wf[KSTEPS * 4 * 2 * 32];          // 2.2 MB
// K-split partial outputs: [4][B][128] fp32
__device__ __align__(16)  float g_part[NSPLIT * (size_t)B_SZ * D_OUT]; // 16.8 MB

// ---------------- PTX helpers ----------------------------------------------
__device__ __forceinline__ void ldm4(uint32_t* a, uint32_t addr) {
    asm volatile("ldmatrix.sync.aligned.m8n8.x4.shared.b16 {%0,%1,%2,%3}, [%4];"
                 : "=r"(a[0]), "=r"(a[1]), "=r"(a[2]), "=r"(a[3]) : "r"(addr));
}
__device__ __forceinline__ void mma16816(float* c, const uint32_t* a,
                                         uint32_t b0, uint32_t b1) {
    asm volatile(
        "mma.sync.aligned.m16n8k16.row.col.f32.f16.f16.f32 "
        "{%0,%1,%2,%3}, {%4,%5,%6,%7}, {%8,%9}, {%0,%1,%2,%3};"
        : "+f"(c[0]), "+f"(c[1]), "+f"(c[2]), "+f"(c[3])
        : "r"(a[0]), "r"(a[1]), "r"(a[2]), "r"(a[3]), "r"(b0), "r"(b1));
}
__device__ __forceinline__ uint32_t h2u(__half2 h) {
    return *reinterpret_cast<uint32_t*>(&h);
}

// ---------------------------------------------------------------------------
// W' prep (validated R7-R15, unchanged).
// ---------------------------------------------------------------------------
__global__ void kan_wprep(const float* __restrict__ w,    // (128, 512, 16)
                          const float* __restrict__ s)    // (128, 512)
{
    const int wc   = blockIdx.y;
    const int lane = threadIdx.x & 31;
    const int ks   = blockIdx.x * 4 + (threadIdx.x >> 5);

    uint32_t r[8];
    #pragma unroll
    for (int nf = 0; nf < 4; nf++) {
        const int n = wc * 32 + nf * 8 + (lane >> 2);
        #pragma unroll
        for (int h = 0; h < 2; h++) {
            const int k = ks * 16 + (lane & 3) * 2 + h * 8;
            float v0, v1;
            if (ks < 512) {
                v0 = w[(size_t)n * 8192 + k];
                v1 = w[(size_t)n * 8192 + k + 1];
            } else {
                const int kk = k - 8192;
                v0 = s[(size_t)n * 512 + kk];
                v1 = s[(size_t)n * 512 + kk + 1];
            }
            r[nf * 2 + h] = h2u(__floats2half2_rn(v0, v1));
        }
    }
    g_wf[((size_t)(ks * 4 + wc) * 2 + 0) * 32 + lane] = make_uint4(r[0], r[1], r[2], r[3]);
    g_wf[((size_t)(ks * 4 + wc) * 2 + 1) * 32 + lane] = make_uint4(r[4], r[5], r[6], r[7]);
}

// ---------------------------------------------------------------------------
// C-chunk builders (128-row tile). Thread: bb = tid>>1 (row), il0 = (tid&1)*4.
// Bank-correct swizzle: byte(b, cb) = b*256 + (cb ^ ((b&7)<<4)).
// ---------------------------------------------------------------------------
__device__ __forceinline__ void build_spline4(char* rb, uint32_t swb,
                                              float4 xv, int il0)
{
    float xs[4] = {xv.x, xv.y, xv.z, xv.w};
    #pragma unroll
    for (int e = 0; e < 4; e++) {
        const int il = il0 + e;
        float p = fminf(fmaxf((xs[e] - X_MIN_F) * SCALE_F, 0.0f), 15.0f);
        int   k0 = min((int)p, 14);
        float f  = p - (float)k0;
        *reinterpret_cast<uint4*>(rb + ((uint32_t)(il * 32)      ^ swb)) = make_uint4(0,0,0,0);
        *reinterpret_cast<uint4*>(rb + ((uint32_t)(il * 32 + 16) ^ swb)) = make_uint4(0,0,0,0);
        const uint32_t cb = (uint32_t)(il * 32 + k0 * 2);
        *reinterpret_cast<__half*>(rb + (cb ^ swb))       = __float2half_rn(1.0f - f);
        *reinterpret_cast<__half*>(rb + ((cb + 2) ^ swb)) = __float2half_rn(f);
    }
}

__device__ __forceinline__ void build_skip4(char* rb, uint32_t swb,
                                            const float* __restrict__ xp, int il0)
{
    #pragma unroll
    for (int v = 0; v < 8; v++) {
        float4 f0 = *reinterpret_cast<const float4*>(xp + v * 8);
        float4 f1 = *reinterpret_cast<const float4*>(xp + v * 8 + 4);
        uint4 pk = make_uint4(h2u(__floats2half2_rn(f0.x, f0.y)),
                              h2u(__floats2half2_rn(f0.z, f0.w)),
                              h2u(__floats2half2_rn(f1.x, f1.y)),
                              h2u(__floats2half2_rn(f1.z, f1.w)));
        *reinterpret_cast<uint4*>(rb + ((uint32_t)(il0 * 32 + v * 16) ^ swb)) = pk;
    }
}

// ---------------------------------------------------------------------------
// Main GEMM: grid (64, 4) = 256 CTAs -> 2 CTAs/SM co-resident (single wave).
// CTA = 128 rows x 128 outs x K'/4 (17 chunks). Warp grid 2(M) x 4(N),
// warp tile 64x32. C double-buffered in SMEM (64KB); B direct-LDG ring.
// ---------------------------------------------------------------------------
__global__ __launch_bounds__(256, 2)
void kan_mma(const float* __restrict__ x)
{
    extern __shared__ __align__(128) char dsm[];
    char* cs = dsm;                     // 2 x 32768 (C: 128 rows x 256B)

    const int tid  = threadIdx.x;
    const int lane = tid & 31;
    const int w    = tid >> 5;
    const int wm   = w >> 2;            // 0..1  (64 rows each)
    const int wc   = w & 3;             // 0..3  (32 outs each)
    const int bt   = blockIdx.x;        // b-tile 0..63 (128 rows each)
    const int ksp  = blockIdx.y;        // K-split 0..3
    const int ch0  = ksp * KPART;
    const int kse  = (ch0 + KPART) * 8; // kstep end

    float acc[4][4][4];                 // [A-frag p][n-frag][4]
    #pragma unroll
    for (int p = 0; p < 4; p++)
        #pragma unroll
        for (int nf = 0; nf < 4; nf++)
            #pragma unroll
            for (int v = 0; v < 4; v++)
                acc[p][nf][v] = 0.0f;

    const uint32_t cs32 = (uint32_t)__cvta_generic_to_shared(cs);
    const uint32_t swz    = (uint32_t)((lane & 7) << 4);
    const uint32_t achunk = (uint32_t)((lane >> 4) << 4);
    const uint32_t arowoff = (uint32_t)((wm * 64 + (lane & 15)) * 256);

    const int bb  = tid >> 1;           // 0..127 (C row)
    const int il0 = (tid & 1) * 4;      // 4 i-slots per thread
    const uint32_t swb = (uint32_t)((bb & 7) << 4);
    const float* xrow = x + (size_t)(bt * 128 + bb) * 512;

    // B fragment stream (direct from L2-resident g_wf).
    const char* gwb = reinterpret_cast<const char*>(g_wf);
    const uint32_t bwoff = (uint32_t)(wc * 1024 + lane * 16);
    auto ldB = [&](int ks, uint4& q0, uint4& q1) {
        const uint4* bp = reinterpret_cast<const uint4*>(gwb + (size_t)ks * 4096 + bwoff);
        q0 = __ldg(bp);
        q1 = __ldg(bp + 32);
    };

    // Depth-2 B register ring: slot ks&1 holds kstep ks.
    uint4 bq[2][2];
    ldB(ch0 * 8,     bq[0][0], bq[0][1]);
    ldB(ch0 * 8 + 1, bq[1][0], bq[1][1]);

    // Build C chunk ch0 (all ch0 in {0,17,34,51} < 64: spline).
    {
        float4 xv = *reinterpret_cast<const float4*>(xrow + ch0 * 8 + il0);
        build_spline4(cs + bb * 256, swb, xv, il0);
    }
    __syncthreads();

    for (int cl = 0; cl < KPART; cl++) {
        const int ch  = ch0 + cl;
        const int cur = cl & 1, nxt = cur ^ 1;

        float4 xpre = make_float4(0.f, 0.f, 0.f, 0.f);
        const bool haveNext  = (cl + 1 < KPART);
        const bool nextSplin = (ch + 1 < 64);
        if (haveNext && nextSplin)
            xpre = *reinterpret_cast<const float4*>(xrow + (ch + 1) * 8 + il0);

        const uint32_t abase = cs32 + (uint32_t)cur * 32768 + arowoff;

        #pragma unroll
        for (int ksl = 0; ksl < 8; ksl++) {
            const int ks = ch * 8 + ksl;
            const int slot = ks & 1;
            const uint4 r0 = bq[slot][0];
            const uint4 r1 = bq[slot][1];
            if (ks + 2 < kse) ldB(ks + 2, bq[slot][0], bq[slot][1]);

            const uint32_t koff = (achunk + (uint32_t)(ksl * 32)) ^ swz;

            #pragma unroll
            for (int p = 0; p < 4; p++) {
                uint32_t a[4];
                ldm4(a, abase + (uint32_t)p * 4096 + koff);
                mma16816(acc[p][0], a, r0.x, r0.y);
                mma16816(acc[p][1], a, r0.z, r0.w);
                mma16816(acc[p][2], a, r1.x, r1.y);
                mma16816(acc[p][3], a, r1.z, r1.w);
            }
        }

        if (haveNext) {
            char* rb = cs + nxt * 32768 + bb * 256;
            if (nextSplin) {
                build_spline4(rb, swb, xpre, il0);
            } else {
                build_skip4(rb, swb, xrow + (ch + 1 - 64) * 128 + il0 * 16, il0);
            }
        }
        __syncthreads();
    }

    // Epilogue: fp32 partials.
    float* yb = g_part + (size_t)ksp * (B_SZ * D_OUT)
                       + (size_t)(bt * 128 + wm * 64) * 128;
    #pragma unroll
    for (int p = 0; p < 4; p++) {
        const int r0 = p * 16 + (lane >> 2);
        #pragma unroll
        for (int nf = 0; nf < 4; nf++) {
            const int n0 = wc * 32 + nf * 8 + (lane & 3) * 2;
            *reinterpret_cast<float2*>(yb + (size_t)r0 * 128 + n0) =
                make_float2(acc[p][nf][0], acc[p][nf][1]);
            *reinterpret_cast<float2*>(yb + (size_t)(r0 + 8) * 128 + n0) =
                make_float2(acc[p][nf][2], acc[p][nf][3]);
        }
    }
}

// ---------------------------------------------------------------------------
// Reduce: y = part0+part1+part2+part3 + bias. grid=1024, block=256.
// ---------------------------------------------------------------------------
__global__ __launch_bounds__(256)
void kan_reduce(const float* __restrict__ bias, float* __restrict__ y)
{
    const int t = blockIdx.x * 256 + threadIdx.x;      // over B*128/4
    const int N4 = B_SZ * D_OUT / 4;
    float4 a = reinterpret_cast<const float4*>(g_part)[t];
    float4 b = reinterpret_cast<const float4*>(g_part)[t + N4];
    float4 c = reinterpret_cast<const float4*>(g_part)[t + 2 * N4];
    float4 d = reinterpret_cast<const float4*>(g_part)[t + 3 * N4];
    float4 bi = reinterpret_cast<const float4*>(bias)[t & 31];
    reinterpret_cast<float4*>(y)[t] =
        make_float4((a.x + b.x) + (c.x + d.x) + bi.x,
                    (a.y + b.y) + (c.y + d.y) + bi.y,
                    (a.z + b.z) + (c.z + d.z) + bi.z,
                    (a.w + b.w) + (c.w + d.w) + bi.w);
}

// ---------------------------------------------------------------------------
// kernel_launch: inputs per metadata order: x, weights, skip_w, bias
// ---------------------------------------------------------------------------
#define SMEM_DYN (64 * 1024)

extern "C" void kernel_launch(void* const* d_in, const int* in_sizes, int n_in,
                              void* d_out, int out_size)
{
    const float* x    = (const float*)d_in[0];
    const float* w    = (const float*)d_in[1];
    const float* skip = (const float*)d_in[2];
    const float* bias = (const float*)d_in[3];
    float* y = (float*)d_out;

    cudaFuncSetAttribute(kan_mma, cudaFuncAttributeMaxDynamicSharedMemorySize,
                         SMEM_DYN);
    kan_wprep<<<dim3(136, 4), 128>>>(w, skip);
    kan_mma<<<dim3(64, NSPLIT), 256, SMEM_DYN>>>(x);
    kan_reduce<<<(B_SZ * D_OUT / 4) / 256, 256>>>(bias, y);
}